// round 1
// baseline (speedup 1.0000x reference)
#include <cuda_runtime.h>
#include <math.h>

// ---------------- problem constants ----------------
#define BB 4
#define CC 128
#define HIMG 192
#define WIMG 192
#define PP (HIMG*WIMG)          // 36864 pixels per image
#define NH 2
#define HD 64
#define BNH (BB*NH)             // 8
#define NCHUNK 64
#define CHUNK_PX (PP/NCHUNK)    // 576

#define ELEMS ((size_t)BB*CC*PP)   // 18,874,368

// ---------------- scratch (device globals; no cudaMalloc allowed) ----------------
__device__ float g_xn[ELEMS];
__device__ float g_t [ELEMS];
__device__ float g_q [ELEMS];
__device__ float g_k [ELEMS];
__device__ float g_v [ELEMS];
__device__ float g_norm_q[BNH*HD];
__device__ float g_norm_k[BNH*HD];
__device__ float g_part[(size_t)BNH*NCHUNK*HD*HD];   // 2M floats
__device__ float g_a[BNH*HD*HD];
__device__ float g_avg[BB*CC];
__device__ float g_max[BB*CC];

__device__ __forceinline__ float gelu_f(float x) {
    return 0.5f * x * (1.0f + erff(x * 0.70710678118654752f));
}

// ---------------- LayerNorm over channel dim per pixel ----------------
__global__ void ln_kernel(const float* __restrict__ x, const float* __restrict__ w,
                          const float* __restrict__ b, float* __restrict__ y) {
    int p = blockIdx.x * blockDim.x + threadIdx.x;
    int bi = blockIdx.y;
    if (p >= PP) return;
    const float* xb = x + (size_t)bi * CC * PP + p;
    float s = 0.f, ss = 0.f;
    #pragma unroll 8
    for (int c = 0; c < CC; c++) {
        float v = xb[(size_t)c * PP];
        s += v; ss += v * v;
    }
    float mu = s * (1.0f / CC);
    float var = ss * (1.0f / CC) - mu * mu;
    float r = rsqrtf(var + 1e-5f);
    float* yb = y + (size_t)bi * CC * PP + p;
    #pragma unroll 8
    for (int c = 0; c < CC; c++) {
        float v = xb[(size_t)c * PP];
        yb[(size_t)c * PP] = (v - mu) * r * w[c] + b[c];
    }
}

// ---------------- depthwise 3x3, pad 1 ----------------
__global__ void dw_kernel(const float* __restrict__ x, const float* __restrict__ w,
                          float* __restrict__ y) {
    int idx = blockIdx.x * 256 + threadIdx.x;
    int bc = blockIdx.y;                       // 0..B*C-1
    if (idx >= PP) return;
    int yy = idx / WIMG, xx = idx % WIMG;
    const float* xp = x + (size_t)bc * PP;
    const float* wc = w + (bc % CC) * 9;
    float acc = 0.f;
    #pragma unroll
    for (int ky = 0; ky < 3; ky++) {
        int sy = yy + ky - 1;
        if ((unsigned)sy >= HIMG) continue;
        #pragma unroll
        for (int kx = 0; kx < 3; kx++) {
            int sx = xx + kx - 1;
            if ((unsigned)sx >= WIMG) continue;
            acc += wc[ky*3+kx] * xp[sy*WIMG + sx];
        }
    }
    y[(size_t)bc * PP + idx] = acc;
}

// ---------------- generic pointwise-conv GEMM: Y[co,p] = sum_k W[co,k]*X[k,p] ----------------
// CO in {64,128}, K in {64,128,256}. GIN: gelu applied to X while loading (K=256 uses X0|X1 concat).
// GOUT: gelu applied to the output. Grid: (PP/BN, n_slabs). 256 threads, 8x8 microtile.
template<int CO, int K, int BN, bool GIN, bool GOUT>
__global__ void __launch_bounds__(256) gemm_pw(
    const float* __restrict__ Wm, long wstride,
    const float* __restrict__ X0, const float* __restrict__ X1, long xstride,
    float* __restrict__ Y, long ystride)
{
    constexpr int BK = 16;
    constexpr int TM = 8, TN = 8;
    constexpr int TX = BN / TN;   // 16 or 32
    constexpr int TY = CO / TM;   // 16 or 8
    static_assert(TX * TY == 256, "bad tiling");
    __shared__ __align__(16) float Ws[BK][CO];
    __shared__ __align__(16) float Xs[BK][BN];

    int tid = threadIdx.x;
    int tx = tid % TX, ty = tid / TX;
    int slab = blockIdx.y;
    int p0 = blockIdx.x * BN;

    const float* Wb  = Wm + (long)slab * wstride;
    const float* Xb0 = X0 + (long)slab * xstride;
    const float* Xb1 = (K == 256) ? (X1 + (long)slab * xstride) : nullptr;
    float* Yb = Y + (long)slab * ystride;

    float acc[TM][TN];
    #pragma unroll
    for (int m = 0; m < TM; m++)
        #pragma unroll
        for (int n = 0; n < TN; n++) acc[m][n] = 0.f;

    constexpr int WE = CO * BK / 256;   // 8 or 4 (contiguous along K)
    constexpr int XE = BK * BN / 256;   // 8 or 16 (contiguous along pixels)

    for (int k0 = 0; k0 < K; k0 += BK) {
        // load W tile, store transposed Ws[k][co]
        #pragma unroll
        for (int e = 0; e < WE; e += 4) {
            int idx = tid * WE + e;
            int co = idx / BK, kk = idx % BK;
            float4 v = *(const float4*)&Wb[(long)co * K + k0 + kk];
            Ws[kk+0][co] = v.x; Ws[kk+1][co] = v.y;
            Ws[kk+2][co] = v.z; Ws[kk+3][co] = v.w;
        }
        // load X tile
        #pragma unroll
        for (int e = 0; e < XE; e += 4) {
            int idx = tid * XE + e;
            int r = idx / BN, px = idx % BN;
            int ci = k0 + r;
            const float* src;
            if (K == 256 && ci >= 128) src = Xb1 + (long)(ci - 128) * PP;
            else                       src = Xb0 + (long)ci * PP;
            float4 v = *(const float4*)&src[p0 + px];
            if (GIN) { v.x = gelu_f(v.x); v.y = gelu_f(v.y); v.z = gelu_f(v.z); v.w = gelu_f(v.w); }
            *(float4*)&Xs[r][px] = v;
        }
        __syncthreads();
        #pragma unroll
        for (int kk = 0; kk < BK; kk++) {
            float wv[TM], xv[TN];
            *(float4*)&wv[0] = *(const float4*)&Ws[kk][ty*TM];
            *(float4*)&wv[4] = *(const float4*)&Ws[kk][ty*TM + 4];
            *(float4*)&xv[0] = *(const float4*)&Xs[kk][tx*TN];
            *(float4*)&xv[4] = *(const float4*)&Xs[kk][tx*TN + 4];
            #pragma unroll
            for (int m = 0; m < TM; m++)
                #pragma unroll
                for (int n = 0; n < TN; n++)
                    acc[m][n] = fmaf(wv[m], xv[n], acc[m][n]);
        }
        __syncthreads();
    }

    #pragma unroll
    for (int m = 0; m < TM; m++) {
        int co = ty * TM + m;
        float* dst = Yb + (long)co * PP + p0 + tx * TN;
        float4 o0, o1;
        if (GOUT) {
            o0 = make_float4(gelu_f(acc[m][0]), gelu_f(acc[m][1]), gelu_f(acc[m][2]), gelu_f(acc[m][3]));
            o1 = make_float4(gelu_f(acc[m][4]), gelu_f(acc[m][5]), gelu_f(acc[m][6]), gelu_f(acc[m][7]));
        } else {
            o0 = make_float4(acc[m][0], acc[m][1], acc[m][2], acc[m][3]);
            o1 = make_float4(acc[m][4], acc[m][5], acc[m][6], acc[m][7]);
        }
        *(float4*)&dst[0] = o0;
        *(float4*)&dst[4] = o1;
    }
}

// ---------------- per-row L2 norm over hw (rows are contiguous channel planes) ----------------
__global__ void rownorm_kernel(const float* __restrict__ q, float* __restrict__ norms) {
    int row = blockIdx.x;                      // 0..511
    const float* r = q + (size_t)row * PP;
    float s = 0.f;
    for (int i = threadIdx.x * 4; i < PP; i += 256 * 4) {
        float4 v = *(const float4*)&r[i];
        s += v.x*v.x + v.y*v.y + v.z*v.z + v.w*v.w;
    }
    __shared__ float sm[256];
    sm[threadIdx.x] = s; __syncthreads();
    for (int o = 128; o > 0; o >>= 1) {
        if (threadIdx.x < o) sm[threadIdx.x] += sm[threadIdx.x + o];
        __syncthreads();
    }
    if (threadIdx.x == 0) norms[row] = fmaxf(sqrtf(sm[0]), 1e-12f);
}

// ---------------- Gram partials: part[bn,ch,i,j] = sum_{p in chunk} q_i[p]*k_j[p] ----------------
__global__ void __launch_bounds__(256) gram_partial(const float* __restrict__ q,
                                                    const float* __restrict__ k,
                                                    float* __restrict__ part) {
    int ch = blockIdx.x, bn = blockIdx.y;
    int p0 = ch * CHUNK_PX;
    const float* qb = q + (size_t)bn * HD * PP;
    const float* kb = k + (size_t)bn * HD * PP;
    __shared__ __align__(16) float qs[16][HD];
    __shared__ __align__(16) float ks[16][HD];
    int tid = threadIdx.x;
    int tx = tid % 16, ty = tid / 16;

    float acc[4][4];
    #pragma unroll
    for (int a = 0; a < 4; a++)
        #pragma unroll
        for (int b = 0; b < 4; b++) acc[a][b] = 0.f;

    int li = tid / 4;             // 0..63 (row)
    int lt = (tid % 4) * 4;       // 0..12 (pixel offset, float4)
    for (int t0 = 0; t0 < CHUNK_PX; t0 += 16) {
        float4 qv4 = *(const float4*)&qb[(size_t)li * PP + p0 + t0 + lt];
        float4 kv4 = *(const float4*)&kb[(size_t)li * PP + p0 + t0 + lt];
        qs[lt+0][li] = qv4.x; qs[lt+1][li] = qv4.y; qs[lt+2][li] = qv4.z; qs[lt+3][li] = qv4.w;
        ks[lt+0][li] = kv4.x; ks[lt+1][li] = kv4.y; ks[lt+2][li] = kv4.z; ks[lt+3][li] = kv4.w;
        __syncthreads();
        #pragma unroll
        for (int t = 0; t < 16; t++) {
            float4 qv = *(const float4*)&qs[t][ty*4];
            float4 kv = *(const float4*)&ks[t][tx*4];
            float qa[4] = {qv.x, qv.y, qv.z, qv.w};
            float ka[4] = {kv.x, kv.y, kv.z, kv.w};
            #pragma unroll
            for (int a = 0; a < 4; a++)
                #pragma unroll
                for (int b = 0; b < 4; b++)
                    acc[a][b] = fmaf(qa[a], ka[b], acc[a][b]);
        }
        __syncthreads();
    }
    float* pb = part + (((size_t)bn * NCHUNK + ch) * HD) * HD;
    #pragma unroll
    for (int a = 0; a < 4; a++) {
        int i = ty * 4 + a;
        #pragma unroll
        for (int b = 0; b < 4; b++)
            pb[i * HD + tx * 4 + b] = acc[a][b];
    }
}

// ---------------- reduce partials, scale/normalize, write attn_weight, softmax -> a ----------------
__global__ void attn_softmax(const float* __restrict__ part, const float* __restrict__ nq,
                             const float* __restrict__ nk, const float* __restrict__ scale,
                             float* __restrict__ attnw_out, float* __restrict__ a) {
    int bn = blockIdx.x;
    int n = bn % NH;
    int warp = threadIdx.x / 32, lane = threadIdx.x % 32;
    float sc = scale[n];
    for (int i = warp; i < HD; i += 8) {
        float v[2];
        #pragma unroll
        for (int h = 0; h < 2; h++) {
            int j = lane + 32 * h;
            float s = 0.f;
            for (int ch = 0; ch < NCHUNK; ch++)
                s += part[(((size_t)bn * NCHUNK + ch) * HD + i) * HD + j];
            s = s * sc / (nq[bn*HD + i] * nk[bn*HD + j]);
            attnw_out[((size_t)bn * HD + i) * HD + j] = s;
            v[h] = s;
        }
        float m = fmaxf(v[0], v[1]);
        #pragma unroll
        for (int o = 16; o; o >>= 1) m = fmaxf(m, __shfl_xor_sync(0xffffffffu, m, o));
        float e0 = expf(v[0] - m), e1 = expf(v[1] - m);
        float s = e0 + e1;
        #pragma unroll
        for (int o = 16; o; o >>= 1) s += __shfl_xor_sync(0xffffffffu, s, o);
        float inv = 1.0f / s;
        a[((size_t)bn * HD + i) * HD + lane]      = e0 * inv;
        a[((size_t)bn * HD + i) * HD + lane + 32] = e1 * inv;
    }
}

// ---------------- spatial avg + max per (b,c) ----------------
__global__ void pool_kernel(const float* __restrict__ x, float* __restrict__ avg,
                            float* __restrict__ mx) {
    int bc = blockIdx.x;
    const float* p = x + (size_t)bc * PP;
    float s = 0.f, m = -INFINITY;
    for (int i = threadIdx.x * 4; i < PP; i += 256 * 4) {
        float4 v = *(const float4*)&p[i];
        s += v.x + v.y + v.z + v.w;
        m = fmaxf(m, fmaxf(fmaxf(v.x, v.y), fmaxf(v.z, v.w)));
    }
    __shared__ float ss[256], sm[256];
    ss[threadIdx.x] = s; sm[threadIdx.x] = m; __syncthreads();
    for (int o = 128; o > 0; o >>= 1) {
        if (threadIdx.x < o) {
            ss[threadIdx.x] += ss[threadIdx.x + o];
            sm[threadIdx.x] = fmaxf(sm[threadIdx.x], sm[threadIdx.x + o]);
        }
        __syncthreads();
    }
    if (threadIdx.x == 0) { avg[bc] = ss[0] * (1.0f / PP); mx[bc] = sm[0]; }
}

// ---------------- ChannelGate MLP -> spec_score ----------------
__global__ void gate_kernel(const float* __restrict__ avg, const float* __restrict__ mx,
                            const float* __restrict__ w1, const float* __restrict__ b1,
                            const float* __restrict__ w2, const float* __restrict__ b2,
                            float* __restrict__ out) {
    __shared__ float ha[8], hm[8];
    int c = threadIdx.x;
    for (int b = 0; b < BB; b++) {
        if (c < 8) {
            float sa = b1[c], sm_ = b1[c];
            for (int cc = 0; cc < CC; cc++) {
                sa  += w1[c*CC + cc] * avg[b*CC + cc];
                sm_ += w1[c*CC + cc] * mx[b*CC + cc];
            }
            ha[c] = fmaxf(sa, 0.f);
            hm[c] = fmaxf(sm_, 0.f);
        }
        __syncthreads();
        float sa = b2[c], sm_ = b2[c];
        #pragma unroll
        for (int j = 0; j < 8; j++) {
            sa  += w2[c*8 + j] * ha[j];
            sm_ += w2[c*8 + j] * hm[j];
        }
        out[b*CC + c] = 1.0f / (1.0f + expf(-(sa + sm_)));
        __syncthreads();
    }
}

// ---------------- host launch ----------------
static float* sym(const void* s) {
    void* p = nullptr;
    cudaGetSymbolAddress(&p, s);
    return (float*)p;
}

extern "C" void kernel_launch(void* const* d_in, const int* in_sizes, int n_in,
                              void* d_out, int out_size) {
    const float* x       = (const float*)d_in[0];
    const float* ln_in_w = (const float*)d_in[1];
    const float* ln_in_b = (const float*)d_in[2];
    const float* wq_pw   = (const float*)d_in[3];
    const float* wq_dw   = (const float*)d_in[4];
    const float* wk_pw   = (const float*)d_in[5];
    const float* wk_dw   = (const float*)d_in[6];
    const float* wv_pw   = (const float*)d_in[7];
    const float* wv_dw   = (const float*)d_in[8];
    const float* scale   = (const float*)d_in[9];
    const float* ln_o_w  = (const float*)d_in[10];
    const float* ln_o_b  = (const float*)d_in[11];
    const float* f1_pw   = (const float*)d_in[12];
    const float* f1_dw   = (const float*)d_in[13];
    const float* f2_pw   = (const float*)d_in[14];
    const float* f2_dw   = (const float*)d_in[15];
    const float* f_out   = (const float*)d_in[16];
    const float* g_w1    = (const float*)d_in[17];
    const float* g_b1    = (const float*)d_in[18];
    const float* g_w2    = (const float*)d_in[19];
    const float* g_b2    = (const float*)d_in[20];
    float* out = (float*)d_out;

    float* xn = sym(g_xn);  float* t  = sym(g_t);
    float* q  = sym(g_q);   float* k  = sym(g_k);   float* v = sym(g_v);
    float* nq = sym(g_norm_q); float* nk = sym(g_norm_k);
    float* part = sym(g_part); float* a = sym(g_a);
    float* avg = sym(g_avg);   float* mx = sym(g_max);

    const long SB = (long)CC * PP;   // per-batch slab, 128-channel tensors
    const long SH = (long)HD * PP;   // per-head slab
    dim3 lnGrid(PP/256, BB);
    dim3 dwGrid(PP/256, BB*CC);
    dim3 gGrid(PP/128, BB);          // pw GEMM, BN=128
    dim3 avGrid(PP/256, BNH);        // a@v GEMM, BN=256

    // 1) LN(x) -> xn
    ln_kernel<<<lnGrid, 256>>>(x, ln_in_w, ln_in_b, xn);
    // 2) QKV: pw -> t, dw -> q/k/v
    gemm_pw<128,128,128,false,false><<<gGrid, 256>>>(wq_pw, 0, xn, nullptr, SB, t, SB);
    dw_kernel<<<dwGrid, 256>>>(t, wq_dw, q);
    gemm_pw<128,128,128,false,false><<<gGrid, 256>>>(wk_pw, 0, xn, nullptr, SB, t, SB);
    dw_kernel<<<dwGrid, 256>>>(t, wk_dw, k);
    gemm_pw<128,128,128,false,false><<<gGrid, 256>>>(wv_pw, 0, xn, nullptr, SB, t, SB);
    dw_kernel<<<dwGrid, 256>>>(t, wv_dw, v);
    // 3) row L2 norms
    rownorm_kernel<<<BB*CC, 256>>>(q, nq);
    rownorm_kernel<<<BB*CC, 256>>>(k, nk);
    // 4) Gram partials + reduce/softmax (also writes attn_weight to d_out+512)
    gram_partial<<<dim3(NCHUNK, BNH), 256>>>(q, k, part);
    attn_softmax<<<BNH, 256>>>(part, nq, nk, scale, out + BB*CC, a);
    // 5) out = a @ v  -> xn (reuse)
    gemm_pw<64,64,256,false,false><<<avGrid, 256>>>(a, (long)HD*HD, v, nullptr, SH, xn, SH);
    // 6) LN(out) -> t
    ln_kernel<<<lnGrid, 256>>>(xn, ln_o_w, ln_o_b, t);
    // 7) FFN branches: pw+GELU -> xn, dw -> q (o1) / k (o2)
    gemm_pw<128,128,128,false,true><<<gGrid, 256>>>(f1_pw, 0, t, nullptr, SB, xn, SB);
    dw_kernel<<<dwGrid, 256>>>(xn, f1_dw, q);
    gemm_pw<128,128,128,false,true><<<gGrid, 256>>>(f2_pw, 0, t, nullptr, SB, xn, SB);
    dw_kernel<<<dwGrid, 256>>>(xn, f2_dw, k);
    // 8) f_out over gelu(cat(o1,o2)) -> v (ffn)
    gemm_pw<128,256,128,true,false><<<gGrid, 256>>>(f_out, 0, q, k, SB, v, SB);
    // 9) ChannelGate
    pool_kernel<<<BB*CC, 256>>>(v, avg, mx);
    gate_kernel<<<1, 128>>>(avg, mx, g_w1, g_b1, g_w2, g_b2, out);
}

// round 3
// speedup vs baseline: 1.2405x; 1.2405x over previous
#include <cuda_runtime.h>
#include <cuda_bf16.h>
#include <math.h>
#include <stdint.h>

// ---------------- problem constants ----------------
#define BB 4
#define CC 128
#define HIMG 192
#define WIMG 192
#define PP (HIMG*WIMG)          // 36864 pixels per image
#define NH 2
#define HD 64
#define BNH (BB*NH)             // 8
#define NCHUNK 64
#define CHUNK_PX (PP/NCHUNK)    // 576

#define ELEMS ((size_t)BB*CC*PP)   // 18,874,368

// ---------------- scratch ----------------
__device__ float g_xn[ELEMS];
__device__ float g_t [ELEMS];
__device__ float g_q [ELEMS];
__device__ float g_k [ELEMS];
__device__ float g_v [ELEMS];
__device__ float g_norm_q[BNH*HD];
__device__ float g_norm_k[BNH*HD];
__device__ float g_part[(size_t)BNH*NCHUNK*HD*HD];
__device__ float g_a[BNH*HD*HD];
__device__ float g_avg[BB*CC];
__device__ float g_max[BB*CC];

__device__ __forceinline__ float gelu_f(float x) {
    return 0.5f * x * (1.0f + erff(x * 0.70710678118654752f));
}

// ================= mma.sync helpers (arch-agnostic PTX) =================
__device__ __forceinline__ uint32_t smem_u32(const void* p) {
    uint32_t a;
    asm("{ .reg .u64 t; cvta.to.shared.u64 t, %1; cvt.u32.u64 %0, t; }" : "=r"(a) : "l"(p));
    return a;
}

__device__ __forceinline__ void ldsm_x4(uint32_t* r, uint32_t addr) {
    asm volatile("ldmatrix.sync.aligned.m8n8.x4.shared.b16 {%0,%1,%2,%3}, [%4];"
        : "=r"(r[0]), "=r"(r[1]), "=r"(r[2]), "=r"(r[3]) : "r"(addr));
}
__device__ __forceinline__ void ldsm_x4_t(uint32_t* r, uint32_t addr) {
    asm volatile("ldmatrix.sync.aligned.m8n8.x4.trans.shared.b16 {%0,%1,%2,%3}, [%4];"
        : "=r"(r[0]), "=r"(r[1]), "=r"(r[2]), "=r"(r[3]) : "r"(addr));
}
__device__ __forceinline__ void mma_bf16(float* c, const uint32_t* a, const uint32_t* b) {
    asm volatile(
        "mma.sync.aligned.m16n8k16.row.col.f32.bf16.bf16.f32 "
        "{%0,%1,%2,%3}, {%4,%5,%6,%7}, {%8,%9}, {%0,%1,%2,%3};"
        : "+f"(c[0]), "+f"(c[1]), "+f"(c[2]), "+f"(c[3])
        : "r"(a[0]), "r"(a[1]), "r"(a[2]), "r"(a[3]), "r"(b[0]), "r"(b[1]));
}

__device__ __forceinline__ void split2(float x, float y, uint32_t& hi, uint32_t& lo) {
    __nv_bfloat16 hx = __float2bfloat16_rn(x);
    __nv_bfloat16 hy = __float2bfloat16_rn(y);
    __nv_bfloat16 lx = __float2bfloat16_rn(x - __bfloat162float(hx));
    __nv_bfloat16 ly = __float2bfloat16_rn(y - __bfloat162float(hy));
    hi = (uint32_t)__bfloat16_as_ushort(hx) | ((uint32_t)__bfloat16_as_ushort(hy) << 16);
    lo = (uint32_t)__bfloat16_as_ushort(lx) | ((uint32_t)__bfloat16_as_ushort(ly) << 16);
}

// ============== tensor-core (HMMA) pointwise GEMM ==============
// Y[co, p] = sum_ci W[co, ci] * X[ci, p], co=128, ci=128*KPASS, per-CTA 128x128 tile.
// bf16 split-product: hi*hi + hi*lo + lo*hi (fp32 accumulate) -> ~4e-6 rel error.
// SMEM rows padded to 136 bf16 (272 B): conflict-free ldmatrix + stores.
#define LDA 136
#define TILE_BYTES (128*LDA*2)          // 34816
#define MM_SMEM (4*TILE_BYTES)          // Ah, Al, Xh, Xl = 139264

template<int KPASS, bool GIN, bool GOUT>
__global__ void __launch_bounds__(256, 1) gemm_mma(
    const float* __restrict__ Wg,
    const float* __restrict__ X0, const float* __restrict__ X1,
    long xstride, float* __restrict__ Y, long ystride)
{
    extern __shared__ __align__(16) char smem[];
    uint32_t sA_hi = smem_u32(smem);
    uint32_t sA_lo = sA_hi + TILE_BYTES;
    uint32_t sX_hi = sA_lo + TILE_BYTES;
    uint32_t sX_lo = sX_hi + TILE_BYTES;

    const int tid = threadIdx.x;
    const int wid = tid >> 5, lane = tid & 31;
    const int bi = blockIdx.y;
    const int p0 = blockIdx.x * 128;
    float* Yb = Y + (long)bi * ystride;

    // warp tiling: 2 (M) x 4 (N); warp tile 64x32
    const int wm = wid & 1, wn = wid >> 1;
    const int m0 = wm * 64, n0 = wn * 32;

    // per-lane ldmatrix offsets
    const int ar = (lane & 7) + ((lane >> 3) & 1) * 8;   // row within 16
    const int ac = ((lane >> 4) & 1) * 8;                // col half
    // A: row = m0 + mt*16 + ar, col = k0 + ac
    const uint32_t offA = (uint32_t)((m0 + ar) * LDA + ac) * 2;
    // B: row = k0 + ar, col = n0 + bt*16 + ac
    const uint32_t offB = (uint32_t)(ar * LDA + n0 + ac) * 2;

    float C[4][4][4];
    #pragma unroll
    for (int mt = 0; mt < 4; mt++)
        #pragma unroll
        for (int nt = 0; nt < 4; nt++)
            #pragma unroll
            for (int e = 0; e < 4; e++) C[mt][nt][e] = 0.f;

    const int WROW = 128 * KPASS;

    #pragma unroll
    for (int pass = 0; pass < KPASS; pass++) {
        if (pass > 0) __syncthreads();

        // ---- stage W[:, pass*128 +: 128] (split) ----
        const float* Wp = Wg + pass * 128;
        #pragma unroll
        for (int it = 0; it < 16; it++) {
            int idx = (it * 256 + tid) * 4;
            int co = idx >> 7, k = idx & 127;
            float4 v = *(const float4*)&Wp[(long)co * WROW + k];
            uint32_t h0, l0, h1, l1;
            split2(v.x, v.y, h0, l0);
            split2(v.z, v.w, h1, l1);
            uint32_t off = (uint32_t)(co * LDA + k) * 2;
            asm volatile("st.shared.v2.b32 [%0], {%1,%2};" :: "r"(sA_hi + off), "r"(h0), "r"(h1));
            asm volatile("st.shared.v2.b32 [%0], {%1,%2};" :: "r"(sA_lo + off), "r"(l0), "r"(l1));
        }
        // ---- stage X tile [128 k][128 px] (split, optional gelu) ----
        const float* Xsrc = ((pass == 0) ? X0 : X1) + (long)bi * xstride;
        #pragma unroll
        for (int it = 0; it < 16; it++) {
            int idx = (it * 256 + tid) * 4;
            int k = idx >> 7, n = idx & 127;
            float4 v = *(const float4*)&Xsrc[(long)k * PP + p0 + n];
            if (GIN) { v.x = gelu_f(v.x); v.y = gelu_f(v.y); v.z = gelu_f(v.z); v.w = gelu_f(v.w); }
            uint32_t h0, l0, h1, l1;
            split2(v.x, v.y, h0, l0);
            split2(v.z, v.w, h1, l1);
            uint32_t off = (uint32_t)(k * LDA + n) * 2;
            asm volatile("st.shared.v2.b32 [%0], {%1,%2};" :: "r"(sX_hi + off), "r"(h0), "r"(h1));
            asm volatile("st.shared.v2.b32 [%0], {%1,%2};" :: "r"(sX_lo + off), "r"(l0), "r"(l1));
        }
        __syncthreads();

        // ---- 3 split products ----
        #pragma unroll
        for (int s = 0; s < 3; s++) {
            uint32_t aBase = (s == 2) ? sA_lo : sA_hi;
            uint32_t bBase = (s == 1) ? sX_lo : sX_hi;
            #pragma unroll
            for (int kk = 0; kk < 8; kk++) {
                int k0 = kk * 16;
                uint32_t af[4][4];
                #pragma unroll
                for (int mt = 0; mt < 4; mt++)
                    ldsm_x4(af[mt], aBase + offA + (uint32_t)(mt * 16 * LDA + k0) * 2);
                uint32_t bf_[2][4];
                #pragma unroll
                for (int bt = 0; bt < 2; bt++)
                    ldsm_x4_t(bf_[bt], bBase + offB + (uint32_t)(k0 * LDA + bt * 16) * 2);
                #pragma unroll
                for (int mt = 0; mt < 4; mt++)
                    #pragma unroll
                    for (int nt = 0; nt < 4; nt++)
                        mma_bf16(C[mt][nt], af[mt], &bf_[nt >> 1][(nt & 1) * 2]);
            }
        }
    }

    // ---- epilogue ----
    const int g = lane >> 2, i2 = (lane & 3) * 2;
    #pragma unroll
    for (int mt = 0; mt < 4; mt++) {
        int row0 = m0 + mt * 16 + g;
        #pragma unroll
        for (int nt = 0; nt < 4; nt++) {
            int p = p0 + n0 + nt * 8 + i2;
            float2 o0 = make_float2(C[mt][nt][0], C[mt][nt][1]);
            float2 o1 = make_float2(C[mt][nt][2], C[mt][nt][3]);
            if (GOUT) {
                o0.x = gelu_f(o0.x); o0.y = gelu_f(o0.y);
                o1.x = gelu_f(o1.x); o1.y = gelu_f(o1.y);
            }
            *(float2*)&Yb[(long)row0 * PP + p]       = o0;
            *(float2*)&Yb[(long)(row0 + 8) * PP + p] = o1;
        }
    }
}

// ---------------- LayerNorm over channel dim per pixel ----------------
__global__ void ln_kernel(const float* __restrict__ x, const float* __restrict__ w,
                          const float* __restrict__ b, float* __restrict__ y) {
    int p = blockIdx.x * blockDim.x + threadIdx.x;
    int bi = blockIdx.y;
    if (p >= PP) return;
    const float* xb = x + (size_t)bi * CC * PP + p;
    float s = 0.f, ss = 0.f;
    #pragma unroll 8
    for (int c = 0; c < CC; c++) {
        float v = xb[(size_t)c * PP];
        s += v; ss += v * v;
    }
    float mu = s * (1.0f / CC);
    float var = ss * (1.0f / CC) - mu * mu;
    float r = rsqrtf(var + 1e-5f);
    float* yb = y + (size_t)bi * CC * PP + p;
    #pragma unroll 8
    for (int c = 0; c < CC; c++) {
        float v = xb[(size_t)c * PP];
        yb[(size_t)c * PP] = (v - mu) * r * w[c] + b[c];
    }
}

// ---------------- depthwise 3x3, pad 1 ----------------
__global__ void dw_kernel(const float* __restrict__ x, const float* __restrict__ w,
                          float* __restrict__ y) {
    int idx = blockIdx.x * 256 + threadIdx.x;
    int bc = blockIdx.y;
    if (idx >= PP) return;
    int yy = idx / WIMG, xx = idx % WIMG;
    const float* xp = x + (size_t)bc * PP;
    const float* wc = w + (bc % CC) * 9;
    float acc = 0.f;
    #pragma unroll
    for (int ky = 0; ky < 3; ky++) {
        int sy = yy + ky - 1;
        if ((unsigned)sy >= HIMG) continue;
        #pragma unroll
        for (int kx = 0; kx < 3; kx++) {
            int sx = xx + kx - 1;
            if ((unsigned)sx >= WIMG) continue;
            acc += wc[ky*3+kx] * xp[sy*WIMG + sx];
        }
    }
    y[(size_t)bc * PP + idx] = acc;
}

// ---------------- fp32 GEMM (kept for a@v) ----------------
template<int CO, int K, int BN, bool GIN, bool GOUT>
__global__ void __launch_bounds__(256) gemm_pw(
    const float* __restrict__ Wm, long wstride,
    const float* __restrict__ X0, const float* __restrict__ X1, long xstride,
    float* __restrict__ Y, long ystride)
{
    constexpr int BK = 16;
    constexpr int TM = 8, TN = 8;
    constexpr int TX = BN / TN;
    constexpr int TY = CO / TM;
    static_assert(TX * TY == 256, "bad tiling");
    __shared__ __align__(16) float Ws[BK][CO];
    __shared__ __align__(16) float Xs[BK][BN];

    int tid = threadIdx.x;
    int tx = tid % TX, ty = tid / TX;
    int slab = blockIdx.y;
    int p0 = blockIdx.x * BN;

    const float* Wb  = Wm + (long)slab * wstride;
    const float* Xb0 = X0 + (long)slab * xstride;
    const float* Xb1 = (K == 256) ? (X1 + (long)slab * xstride) : nullptr;
    float* Yb = Y + (long)slab * ystride;

    float acc[TM][TN];
    #pragma unroll
    for (int m = 0; m < TM; m++)
        #pragma unroll
        for (int n = 0; n < TN; n++) acc[m][n] = 0.f;

    constexpr int WE = CO * BK / 256;
    constexpr int XE = BK * BN / 256;

    for (int k0 = 0; k0 < K; k0 += BK) {
        #pragma unroll
        for (int e = 0; e < WE; e += 4) {
            int idx = tid * WE + e;
            int co = idx / BK, kk = idx % BK;
            float4 v = *(const float4*)&Wb[(long)co * K + k0 + kk];
            Ws[kk+0][co] = v.x; Ws[kk+1][co] = v.y;
            Ws[kk+2][co] = v.z; Ws[kk+3][co] = v.w;
        }
        #pragma unroll
        for (int e = 0; e < XE; e += 4) {
            int idx = tid * XE + e;
            int r = idx / BN, px = idx % BN;
            int ci = k0 + r;
            const float* src;
            if (K == 256 && ci >= 128) src = Xb1 + (long)(ci - 128) * PP;
            else                       src = Xb0 + (long)ci * PP;
            float4 v = *(const float4*)&src[p0 + px];
            if (GIN) { v.x = gelu_f(v.x); v.y = gelu_f(v.y); v.z = gelu_f(v.z); v.w = gelu_f(v.w); }
            *(float4*)&Xs[r][px] = v;
        }
        __syncthreads();
        #pragma unroll
        for (int kk = 0; kk < BK; kk++) {
            float wv[TM], xv[TN];
            *(float4*)&wv[0] = *(const float4*)&Ws[kk][ty*TM];
            *(float4*)&wv[4] = *(const float4*)&Ws[kk][ty*TM + 4];
            *(float4*)&xv[0] = *(const float4*)&Xs[kk][tx*TN];
            *(float4*)&xv[4] = *(const float4*)&Xs[kk][tx*TN + 4];
            #pragma unroll
            for (int m = 0; m < TM; m++)
                #pragma unroll
                for (int n = 0; n < TN; n++)
                    acc[m][n] = fmaf(wv[m], xv[n], acc[m][n]);
        }
        __syncthreads();
    }

    #pragma unroll
    for (int m = 0; m < TM; m++) {
        int co = ty * TM + m;
        float* dst = Yb + (long)co * PP + p0 + tx * TN;
        float4 o0, o1;
        if (GOUT) {
            o0 = make_float4(gelu_f(acc[m][0]), gelu_f(acc[m][1]), gelu_f(acc[m][2]), gelu_f(acc[m][3]));
            o1 = make_float4(gelu_f(acc[m][4]), gelu_f(acc[m][5]), gelu_f(acc[m][6]), gelu_f(acc[m][7]));
        } else {
            o0 = make_float4(acc[m][0], acc[m][1], acc[m][2], acc[m][3]);
            o1 = make_float4(acc[m][4], acc[m][5], acc[m][6], acc[m][7]);
        }
        *(float4*)&dst[0] = o0;
        *(float4*)&dst[4] = o1;
    }
}

// ---------------- per-row L2 norm ----------------
__global__ void rownorm_kernel(const float* __restrict__ q, float* __restrict__ norms) {
    int row = blockIdx.x;
    const float* r = q + (size_t)row * PP;
    float s = 0.f;
    for (int i = threadIdx.x * 4; i < PP; i += 256 * 4) {
        float4 v = *(const float4*)&r[i];
        s += v.x*v.x + v.y*v.y + v.z*v.z + v.w*v.w;
    }
    __shared__ float sm[256];
    sm[threadIdx.x] = s; __syncthreads();
    for (int o = 128; o > 0; o >>= 1) {
        if (threadIdx.x < o) sm[threadIdx.x] += sm[threadIdx.x + o];
        __syncthreads();
    }
    if (threadIdx.x == 0) norms[row] = fmaxf(sqrtf(sm[0]), 1e-12f);
}

// ---------------- Gram partials ----------------
__global__ void __launch_bounds__(256) gram_partial(const float* __restrict__ q,
                                                    const float* __restrict__ k,
                                                    float* __restrict__ part) {
    int ch = blockIdx.x, bn = blockIdx.y;
    int p0 = ch * CHUNK_PX;
    const float* qb = q + (size_t)bn * HD * PP;
    const float* kb = k + (size_t)bn * HD * PP;
    __shared__ __align__(16) float qs[16][HD];
    __shared__ __align__(16) float ks[16][HD];
    int tid = threadIdx.x;
    int tx = tid % 16, ty = tid / 16;

    float acc[4][4];
    #pragma unroll
    for (int a = 0; a < 4; a++)
        #pragma unroll
        for (int b = 0; b < 4; b++) acc[a][b] = 0.f;

    int li = tid / 4;
    int lt = (tid % 4) * 4;
    for (int t0 = 0; t0 < CHUNK_PX; t0 += 16) {
        float4 qv4 = *(const float4*)&qb[(size_t)li * PP + p0 + t0 + lt];
        float4 kv4 = *(const float4*)&kb[(size_t)li * PP + p0 + t0 + lt];
        qs[lt+0][li] = qv4.x; qs[lt+1][li] = qv4.y; qs[lt+2][li] = qv4.z; qs[lt+3][li] = qv4.w;
        ks[lt+0][li] = kv4.x; ks[lt+1][li] = kv4.y; ks[lt+2][li] = kv4.z; ks[lt+3][li] = kv4.w;
        __syncthreads();
        #pragma unroll
        for (int t = 0; t < 16; t++) {
            float4 qv = *(const float4*)&qs[t][ty*4];
            float4 kv = *(const float4*)&ks[t][tx*4];
            float qa[4] = {qv.x, qv.y, qv.z, qv.w};
            float ka[4] = {kv.x, kv.y, kv.z, kv.w};
            #pragma unroll
            for (int a = 0; a < 4; a++)
                #pragma unroll
                for (int b = 0; b < 4; b++)
                    acc[a][b] = fmaf(qa[a], ka[b], acc[a][b]);
        }
        __syncthreads();
    }
    float* pb = part + (((size_t)bn * NCHUNK + ch) * HD) * HD;
    #pragma unroll
    for (int a = 0; a < 4; a++) {
        int i = ty * 4 + a;
        #pragma unroll
        for (int b = 0; b < 4; b++)
            pb[i * HD + tx * 4 + b] = acc[a][b];
    }
}

// ---------------- reduce + softmax ----------------
__global__ void attn_softmax(const float* __restrict__ part, const float* __restrict__ nq,
                             const float* __restrict__ nk, const float* __restrict__ scale,
                             float* __restrict__ attnw_out, float* __restrict__ a) {
    int bn = blockIdx.x;
    int n = bn % NH;
    int warp = threadIdx.x / 32, lane = threadIdx.x % 32;
    float sc = scale[n];
    for (int i = warp; i < HD; i += 8) {
        float v[2];
        #pragma unroll
        for (int h = 0; h < 2; h++) {
            int j = lane + 32 * h;
            float s = 0.f;
            for (int ch = 0; ch < NCHUNK; ch++)
                s += part[(((size_t)bn * NCHUNK + ch) * HD + i) * HD + j];
            s = s * sc / (nq[bn*HD + i] * nk[bn*HD + j]);
            attnw_out[((size_t)bn * HD + i) * HD + j] = s;
            v[h] = s;
        }
        float m = fmaxf(v[0], v[1]);
        #pragma unroll
        for (int o = 16; o; o >>= 1) m = fmaxf(m, __shfl_xor_sync(0xffffffffu, m, o));
        float e0 = expf(v[0] - m), e1 = expf(v[1] - m);
        float s = e0 + e1;
        #pragma unroll
        for (int o = 16; o; o >>= 1) s += __shfl_xor_sync(0xffffffffu, s, o);
        float inv = 1.0f / s;
        a[((size_t)bn * HD + i) * HD + lane]      = e0 * inv;
        a[((size_t)bn * HD + i) * HD + lane + 32] = e1 * inv;
    }
}

// ---------------- spatial avg + max ----------------
__global__ void pool_kernel(const float* __restrict__ x, float* __restrict__ avg,
                            float* __restrict__ mx) {
    int bc = blockIdx.x;
    const float* p = x + (size_t)bc * PP;
    float s = 0.f, m = -INFINITY;
    for (int i = threadIdx.x * 4; i < PP; i += 256 * 4) {
        float4 v = *(const float4*)&p[i];
        s += v.x + v.y + v.z + v.w;
        m = fmaxf(m, fmaxf(fmaxf(v.x, v.y), fmaxf(v.z, v.w)));
    }
    __shared__ float ss[256], sm[256];
    ss[threadIdx.x] = s; sm[threadIdx.x] = m; __syncthreads();
    for (int o = 128; o > 0; o >>= 1) {
        if (threadIdx.x < o) {
            ss[threadIdx.x] += ss[threadIdx.x + o];
            sm[threadIdx.x] = fmaxf(sm[threadIdx.x], sm[threadIdx.x + o]);
        }
        __syncthreads();
    }
    if (threadIdx.x == 0) { avg[bc] = ss[0] * (1.0f / PP); mx[bc] = sm[0]; }
}

// ---------------- ChannelGate MLP ----------------
__global__ void gate_kernel(const float* __restrict__ avg, const float* __restrict__ mx,
                            const float* __restrict__ w1, const float* __restrict__ b1,
                            const float* __restrict__ w2, const float* __restrict__ b2,
                            float* __restrict__ out) {
    __shared__ float ha[8], hm[8];
    int c = threadIdx.x;
    for (int b = 0; b < BB; b++) {
        if (c < 8) {
            float sa = b1[c], sm_ = b1[c];
            for (int cc = 0; cc < CC; cc++) {
                sa  += w1[c*CC + cc] * avg[b*CC + cc];
                sm_ += w1[c*CC + cc] * mx[b*CC + cc];
            }
            ha[c] = fmaxf(sa, 0.f);
            hm[c] = fmaxf(sm_, 0.f);
        }
        __syncthreads();
        float sa = b2[c], sm_ = b2[c];
        #pragma unroll
        for (int j = 0; j < 8; j++) {
            sa  += w2[c*8 + j] * ha[j];
            sm_ += w2[c*8 + j] * hm[j];
        }
        out[b*CC + c] = 1.0f / (1.0f + expf(-(sa + sm_)));
        __syncthreads();
    }
}

// ---------------- host launch ----------------
static float* sym(const void* s) {
    void* p = nullptr;
    cudaGetSymbolAddress(&p, s);
    return (float*)p;
}

extern "C" void kernel_launch(void* const* d_in, const int* in_sizes, int n_in,
                              void* d_out, int out_size) {
    const float* x       = (const float*)d_in[0];
    const float* ln_in_w = (const float*)d_in[1];
    const float* ln_in_b = (const float*)d_in[2];
    const float* wq_pw   = (const float*)d_in[3];
    const float* wq_dw   = (const float*)d_in[4];
    const float* wk_pw   = (const float*)d_in[5];
    const float* wk_dw   = (const float*)d_in[6];
    const float* wv_pw   = (const float*)d_in[7];
    const float* wv_dw   = (const float*)d_in[8];
    const float* scale   = (const float*)d_in[9];
    const float* ln_o_w  = (const float*)d_in[10];
    const float* ln_o_b  = (const float*)d_in[11];
    const float* f1_pw   = (const float*)d_in[12];
    const float* f1_dw   = (const float*)d_in[13];
    const float* f2_pw   = (const float*)d_in[14];
    const float* f2_dw   = (const float*)d_in[15];
    const float* f_out   = (const float*)d_in[16];
    const float* g_w1    = (const float*)d_in[17];
    const float* g_b1    = (const float*)d_in[18];
    const float* g_w2    = (const float*)d_in[19];
    const float* g_b2    = (const float*)d_in[20];
    float* out = (float*)d_out;

    float* xn = sym(g_xn);  float* t  = sym(g_t);
    float* q  = sym(g_q);   float* k  = sym(g_k);   float* v = sym(g_v);
    float* nq = sym(g_norm_q); float* nk = sym(g_norm_k);
    float* part = sym(g_part); float* a = sym(g_a);
    float* avg = sym(g_avg);   float* mx = sym(g_max);

    cudaFuncSetAttribute(gemm_mma<1,false,false>, cudaFuncAttributeMaxDynamicSharedMemorySize, MM_SMEM);
    cudaFuncSetAttribute(gemm_mma<1,false,true>,  cudaFuncAttributeMaxDynamicSharedMemorySize, MM_SMEM);
    cudaFuncSetAttribute(gemm_mma<2,true,false>,  cudaFuncAttributeMaxDynamicSharedMemorySize, MM_SMEM);

    const long SB = (long)CC * PP;
    const long SH = (long)HD * PP;
    dim3 lnGrid(PP/256, BB);
    dim3 dwGrid(PP/256, BB*CC);
    dim3 mmGrid(PP/128, BB);        // HMMA pw GEMM, 128 px/CTA
    dim3 avGrid(PP/256, BNH);

    // 1) LN(x) -> xn
    ln_kernel<<<lnGrid, 256>>>(x, ln_in_w, ln_in_b, xn);
    // 2) QKV: pw (HMMA) -> t, dw -> q/k/v
    gemm_mma<1,false,false><<<mmGrid, 256, MM_SMEM>>>(wq_pw, xn, nullptr, SB, t, SB);
    dw_kernel<<<dwGrid, 256>>>(t, wq_dw, q);
    gemm_mma<1,false,false><<<mmGrid, 256, MM_SMEM>>>(wk_pw, xn, nullptr, SB, t, SB);
    dw_kernel<<<dwGrid, 256>>>(t, wk_dw, k);
    gemm_mma<1,false,false><<<mmGrid, 256, MM_SMEM>>>(wv_pw, xn, nullptr, SB, t, SB);
    dw_kernel<<<dwGrid, 256>>>(t, wv_dw, v);
    // 3) row L2 norms
    rownorm_kernel<<<BB*CC, 256>>>(q, nq);
    rownorm_kernel<<<BB*CC, 256>>>(k, nk);
    // 4) Gram partials + softmax (writes attn_weight to d_out+512)
    gram_partial<<<dim3(NCHUNK, BNH), 256>>>(q, k, part);
    attn_softmax<<<BNH, 256>>>(part, nq, nk, scale, out + BB*CC, a);
    // 5) out = a @ v -> xn
    gemm_pw<64,64,256,false,false><<<avGrid, 256>>>(a, (long)HD*HD, v, nullptr, SH, xn, SH);
    // 6) LN(out) -> t
    ln_kernel<<<lnGrid, 256>>>(xn, ln_o_w, ln_o_b, t);
    // 7) FFN branches (HMMA pw + GELU out) -> xn, dw -> q/k
    gemm_mma<1,false,true><<<mmGrid, 256, MM_SMEM>>>(f1_pw, t, nullptr, SB, xn, SB);
    dw_kernel<<<dwGrid, 256>>>(xn, f1_dw, q);
    gemm_mma<1,false,true><<<mmGrid, 256, MM_SMEM>>>(f2_pw, t, nullptr, SB, xn, SB);
    dw_kernel<<<dwGrid, 256>>>(xn, f2_dw, k);
    // 8) f_out over gelu(cat(o1,o2)) -> v (K=256, 2 passes)
    gemm_mma<2,true,false><<<mmGrid, 256, MM_SMEM>>>(f_out, q, k, SB, v, SB);
    // 9) ChannelGate
    pool_kernel<<<BB*CC, 256>>>(v, avg, mx);
    gate_kernel<<<1, 128>>>(avg, mx, g_w1, g_b1, g_w2, g_b2, out);
}

// round 4
// speedup vs baseline: 1.5518x; 1.2509x over previous
#include <cuda_runtime.h>
#include <cuda_bf16.h>
#include <math.h>
#include <stdint.h>

// ---------------- problem constants ----------------
#define BB 4
#define CC 128
#define HIMG 192
#define WIMG 192
#define PP (HIMG*WIMG)          // 36864
#define NH 2
#define HD 64
#define BNH (BB*NH)             // 8
#define NCHUNK 64
#define CHUNK_PX (PP/NCHUNK)    // 576
#define NBX (PP/128)            // 288 gemm CTAs per image
#define NDW (PP/1024)           // 36 dw blocks per plane

#define ELEMS ((size_t)BB*CC*PP)

// ---------------- scratch ----------------
__device__ float g_t [ELEMS];
__device__ float g_t2[ELEMS];
__device__ float g_t3[ELEMS];
__device__ float g_q [ELEMS];
__device__ float g_k [ELEMS];
__device__ float g_v [ELEMS];
__device__ float g_norm_q[BB*CC];
__device__ float g_norm_k[BB*CC];
__device__ float g_part[(size_t)BNH*NCHUNK*HD*HD];
__device__ float g_a[BNH*HD*HD];
__device__ float g_sqq[BB*CC*NDW];
__device__ float g_sqk[BB*CC*NDW];
__device__ float g_psum[BB*CC*NBX];
__device__ float g_pmax[BB*CC*NBX];

__device__ __forceinline__ float gelu_f(float x) {
    return 0.5f * x * (1.0f + erff(x * 0.70710678118654752f));
}

// ================= mma.sync helpers =================
__device__ __forceinline__ uint32_t smem_u32(const void* p) {
    uint32_t a;
    asm("{ .reg .u64 t; cvta.to.shared.u64 t, %1; cvt.u32.u64 %0, t; }" : "=r"(a) : "l"(p));
    return a;
}
__device__ __forceinline__ void ldsm_x4(uint32_t* r, uint32_t addr) {
    asm volatile("ldmatrix.sync.aligned.m8n8.x4.shared.b16 {%0,%1,%2,%3}, [%4];"
        : "=r"(r[0]), "=r"(r[1]), "=r"(r[2]), "=r"(r[3]) : "r"(addr));
}
__device__ __forceinline__ void ldsm_x4_t(uint32_t* r, uint32_t addr) {
    asm volatile("ldmatrix.sync.aligned.m8n8.x4.trans.shared.b16 {%0,%1,%2,%3}, [%4];"
        : "=r"(r[0]), "=r"(r[1]), "=r"(r[2]), "=r"(r[3]) : "r"(addr));
}
__device__ __forceinline__ void mma_bf16(float* c, const uint32_t* a, const uint32_t* b) {
    asm volatile(
        "mma.sync.aligned.m16n8k16.row.col.f32.bf16.bf16.f32 "
        "{%0,%1,%2,%3}, {%4,%5,%6,%7}, {%8,%9}, {%0,%1,%2,%3};"
        : "+f"(c[0]), "+f"(c[1]), "+f"(c[2]), "+f"(c[3])
        : "r"(a[0]), "r"(a[1]), "r"(a[2]), "r"(a[3]), "r"(b[0]), "r"(b[1]));
}
__device__ __forceinline__ void split2(float x, float y, uint32_t& hi, uint32_t& lo) {
    __nv_bfloat16 hx = __float2bfloat16_rn(x);
    __nv_bfloat16 hy = __float2bfloat16_rn(y);
    __nv_bfloat16 lx = __float2bfloat16_rn(x - __bfloat162float(hx));
    __nv_bfloat16 ly = __float2bfloat16_rn(y - __bfloat162float(hy));
    hi = (uint32_t)__bfloat16_as_ushort(hx) | ((uint32_t)__bfloat16_as_ushort(hy) << 16);
    lo = (uint32_t)__bfloat16_as_ushort(lx) | ((uint32_t)__bfloat16_as_ushort(ly) << 16);
}

// ============== fused HMMA pointwise GEMM ==============
// Y_s[co,p] = sum_ci W_s[co,ci] * X[ci,p];  co=128, ci=128*KPASS, 128x128 CTA tile.
// bf16 split-product (hi*hi + lo*hi + hi*lo), fp32 accum.
// LNIN: per-pixel channel-LayerNorm applied while staging X.
// POOL: epilogue reduces per-row sum/max into partial buffers instead of storing.
#define LDA 136
#define TILE_BYTES (128*LDA*2)                  // 34816
#define MM_SMEM   (4*TILE_BYTES)                // 139264
#define XF_FLOATS (128*132)
#define MM_SMEM_LN (MM_SMEM + (XF_FLOATS + 768)*4)   // 209920

template<int KPASS, int NSET, bool LNIN, bool GIN, bool GOUT, bool POOL, bool STORE>
__global__ void __launch_bounds__(256, 1) gemm_fused(
    const float* __restrict__ W0, const float* __restrict__ W1, const float* __restrict__ W2,
    const float* __restrict__ X0, const float* __restrict__ X1, long xstride,
    const float* __restrict__ lnw, const float* __restrict__ lnb,
    float* __restrict__ Y0, float* __restrict__ Y1, float* __restrict__ Y2, long ystride,
    float* __restrict__ psum, float* __restrict__ pmax)
{
    extern __shared__ __align__(16) char smem[];
    uint32_t sX_hi = smem_u32(smem);
    uint32_t sX_lo = sX_hi + TILE_BYTES;
    uint32_t sW_hi = sX_lo + TILE_BYTES;
    uint32_t sW_lo = sW_hi + TILE_BYTES;
    float* Xf    = (float*)(smem + MM_SMEM);      // [128][132] (LNIN only)
    float* stats = Xf + XF_FLOATS;                // 768 floats

    const int tid = threadIdx.x;
    const int wid = tid >> 5, lane = tid & 31;
    const int bi = blockIdx.y;
    const int p0 = blockIdx.x * 128;

    const int wm = wid & 1, wn = wid >> 1;
    const int m0 = wm * 64, n0 = wn * 32;
    const int ar = (lane & 7) + ((lane >> 3) & 1) * 8;
    const int ac = ((lane >> 4) & 1) * 8;
    const uint32_t offW = (uint32_t)((m0 + ar) * LDA + ac) * 2;
    const uint32_t offX = (uint32_t)(ar * LDA + n0 + ac) * 2;

    float C[4][4][4];
    if (KPASS > 1) {
        #pragma unroll
        for (int mt = 0; mt < 4; mt++)
            #pragma unroll
            for (int nt = 0; nt < 4; nt++)
                #pragma unroll
                for (int e = 0; e < 4; e++) C[mt][nt][e] = 0.f;
    }

    const int WROW = 128 * KPASS;

    #pragma unroll
    for (int pass = 0; pass < KPASS; pass++) {
        if (pass > 0) __syncthreads();
        const float* Xsrc = ((pass == 0) ? X0 : X1) + (long)bi * xstride;

        if (LNIN) {
            // raw load
            #pragma unroll
            for (int it = 0; it < 16; it++) {
                int idx = (it * 256 + tid) * 4;
                int kk = idx >> 7, nn = idx & 127;
                *(float4*)&Xf[kk * 132 + nn] = *(const float4*)&Xsrc[(long)kk * PP + p0 + nn];
            }
            __syncthreads();
            // per-pixel stats over 128 channels
            {
                int col = tid & 127, half = tid >> 7;
                float s = 0.f, q2 = 0.f;
                int r0 = half * 64;
                #pragma unroll 8
                for (int r = 0; r < 64; r++) {
                    float v = Xf[(r0 + r) * 132 + col];
                    s += v; q2 += v * v;
                }
                stats[half * 128 + col] = s;
                stats[256 + half * 128 + col] = q2;
            }
            __syncthreads();
            if (tid < 128) {
                float s = stats[tid] + stats[128 + tid];
                float q2 = stats[256 + tid] + stats[384 + tid];
                float mu = s * (1.0f / 128.0f);
                float var = q2 * (1.0f / 128.0f) - mu * mu;
                stats[512 + tid] = mu;
                stats[640 + tid] = rsqrtf(var + 1e-5f);
            }
            __syncthreads();
            // normalize + split
            #pragma unroll
            for (int it = 0; it < 16; it++) {
                int idx = (it * 256 + tid) * 4;
                int kk = idx >> 7, nn = idx & 127;
                float4 v = *(float4*)&Xf[kk * 132 + nn];
                float wc = __ldg(&lnw[kk]), bc = __ldg(&lnb[kk]);
                v.x = (v.x - stats[512 + nn + 0]) * stats[640 + nn + 0] * wc + bc;
                v.y = (v.y - stats[512 + nn + 1]) * stats[640 + nn + 1] * wc + bc;
                v.z = (v.z - stats[512 + nn + 2]) * stats[640 + nn + 2] * wc + bc;
                v.w = (v.w - stats[512 + nn + 3]) * stats[640 + nn + 3] * wc + bc;
                uint32_t h0, l0, h1, l1;
                split2(v.x, v.y, h0, l0);
                split2(v.z, v.w, h1, l1);
                uint32_t off = (uint32_t)(kk * LDA + nn) * 2;
                asm volatile("st.shared.v2.b32 [%0], {%1,%2};" :: "r"(sX_hi + off), "r"(h0), "r"(h1));
                asm volatile("st.shared.v2.b32 [%0], {%1,%2};" :: "r"(sX_lo + off), "r"(l0), "r"(l1));
            }
        } else {
            #pragma unroll
            for (int it = 0; it < 16; it++) {
                int idx = (it * 256 + tid) * 4;
                int kk = idx >> 7, nn = idx & 127;
                float4 v = *(const float4*)&Xsrc[(long)kk * PP + p0 + nn];
                if (GIN) { v.x = gelu_f(v.x); v.y = gelu_f(v.y); v.z = gelu_f(v.z); v.w = gelu_f(v.w); }
                uint32_t h0, l0, h1, l1;
                split2(v.x, v.y, h0, l0);
                split2(v.z, v.w, h1, l1);
                uint32_t off = (uint32_t)(kk * LDA + nn) * 2;
                asm volatile("st.shared.v2.b32 [%0], {%1,%2};" :: "r"(sX_hi + off), "r"(h0), "r"(h1));
                asm volatile("st.shared.v2.b32 [%0], {%1,%2};" :: "r"(sX_lo + off), "r"(l0), "r"(l1));
            }
        }

        #pragma unroll
        for (int s = 0; s < NSET; s++) {
            if (pass > 0 || s > 0) __syncthreads();
            const float* Wg = (s == 0) ? W0 : ((s == 1) ? W1 : W2);
            #pragma unroll
            for (int it = 0; it < 16; it++) {
                int idx = (it * 256 + tid) * 4;
                int co = idx >> 7, k = idx & 127;
                float4 v = *(const float4*)&Wg[(long)co * WROW + pass * 128 + k];
                uint32_t h0, l0, h1, l1;
                split2(v.x, v.y, h0, l0);
                split2(v.z, v.w, h1, l1);
                uint32_t off = (uint32_t)(co * LDA + k) * 2;
                asm volatile("st.shared.v2.b32 [%0], {%1,%2};" :: "r"(sW_hi + off), "r"(h0), "r"(h1));
                asm volatile("st.shared.v2.b32 [%0], {%1,%2};" :: "r"(sW_lo + off), "r"(l0), "r"(l1));
            }
            __syncthreads();

            if (KPASS == 1) {
                #pragma unroll
                for (int mt = 0; mt < 4; mt++)
                    #pragma unroll
                    for (int nt = 0; nt < 4; nt++)
                        #pragma unroll
                        for (int e = 0; e < 4; e++) C[mt][nt][e] = 0.f;
            }

            // 3 split products
            #pragma unroll
            for (int s3 = 0; s3 < 3; s3++) {
                uint32_t aBase = (s3 == 2) ? sW_lo : sW_hi;
                uint32_t bBase = (s3 == 1) ? sX_lo : sX_hi;
                #pragma unroll
                for (int kk = 0; kk < 8; kk++) {
                    int k0 = kk * 16;
                    uint32_t af[4][4];
                    #pragma unroll
                    for (int mt = 0; mt < 4; mt++)
                        ldsm_x4(af[mt], aBase + offW + (uint32_t)(mt * 16 * LDA + k0) * 2);
                    uint32_t bf_[2][4];
                    #pragma unroll
                    for (int bt = 0; bt < 2; bt++)
                        ldsm_x4_t(bf_[bt], bBase + offX + (uint32_t)(k0 * LDA + bt * 16) * 2);
                    #pragma unroll
                    for (int mt = 0; mt < 4; mt++)
                        #pragma unroll
                        for (int nt = 0; nt < 4; nt++)
                            mma_bf16(C[mt][nt], af[mt], &bf_[nt >> 1][(nt & 1) * 2]);
                }
            }

            if (KPASS == 1 && STORE) {
                float* Yb = ((s == 0) ? Y0 : ((s == 1) ? Y1 : Y2)) + (long)bi * ystride;
                const int g = lane >> 2, i2 = (lane & 3) * 2;
                #pragma unroll
                for (int mt = 0; mt < 4; mt++) {
                    int row0 = m0 + mt * 16 + g;
                    #pragma unroll
                    for (int nt = 0; nt < 4; nt++) {
                        int p = p0 + n0 + nt * 8 + i2;
                        float2 o0 = make_float2(C[mt][nt][0], C[mt][nt][1]);
                        float2 o1 = make_float2(C[mt][nt][2], C[mt][nt][3]);
                        if (GOUT) {
                            o0.x = gelu_f(o0.x); o0.y = gelu_f(o0.y);
                            o1.x = gelu_f(o1.x); o1.y = gelu_f(o1.y);
                        }
                        *(float2*)&Yb[(long)row0 * PP + p]       = o0;
                        *(float2*)&Yb[(long)(row0 + 8) * PP + p] = o1;
                    }
                }
            }
        }
    }

    if (KPASS > 1 && STORE) {
        float* Yb = Y0 + (long)bi * ystride;
        const int g = lane >> 2, i2 = (lane & 3) * 2;
        #pragma unroll
        for (int mt = 0; mt < 4; mt++) {
            int row0 = m0 + mt * 16 + g;
            #pragma unroll
            for (int nt = 0; nt < 4; nt++) {
                int p = p0 + n0 + nt * 8 + i2;
                float2 o0 = make_float2(C[mt][nt][0], C[mt][nt][1]);
                float2 o1 = make_float2(C[mt][nt][2], C[mt][nt][3]);
                if (GOUT) {
                    o0.x = gelu_f(o0.x); o0.y = gelu_f(o0.y);
                    o1.x = gelu_f(o1.x); o1.y = gelu_f(o1.y);
                }
                *(float2*)&Yb[(long)row0 * PP + p]       = o0;
                *(float2*)&Yb[(long)(row0 + 8) * PP + p] = o1;
            }
        }
    }

    if (POOL) {
        __syncthreads();              // MMAs done; reuse smem front for pool
        float* ps = (float*)smem;     // [128][4]
        float* pm = ps + 512;         // [128][4]
        const int g = lane >> 2;
        #pragma unroll
        for (int mt = 0; mt < 4; mt++) {
            float s0 = 0.f, s1 = 0.f, m0v = -INFINITY, m1v = -INFINITY;
            #pragma unroll
            for (int nt = 0; nt < 4; nt++) {
                s0 += C[mt][nt][0] + C[mt][nt][1];
                m0v = fmaxf(m0v, fmaxf(C[mt][nt][0], C[mt][nt][1]));
                s1 += C[mt][nt][2] + C[mt][nt][3];
                m1v = fmaxf(m1v, fmaxf(C[mt][nt][2], C[mt][nt][3]));
            }
            #pragma unroll
            for (int o = 1; o <= 2; o <<= 1) {
                s0 += __shfl_xor_sync(0xffffffffu, s0, o);
                s1 += __shfl_xor_sync(0xffffffffu, s1, o);
                m0v = fmaxf(m0v, __shfl_xor_sync(0xffffffffu, m0v, o));
                m1v = fmaxf(m1v, __shfl_xor_sync(0xffffffffu, m1v, o));
            }
            if ((lane & 3) == 0) {
                int r0 = m0 + mt * 16 + g;
                ps[r0 * 4 + wn] = s0;       pm[r0 * 4 + wn] = m0v;
                ps[(r0 + 8) * 4 + wn] = s1; pm[(r0 + 8) * 4 + wn] = m1v;
            }
        }
        __syncthreads();
        if (tid < 128) {
            float s = ps[tid*4] + ps[tid*4+1] + ps[tid*4+2] + ps[tid*4+3];
            float m = fmaxf(fmaxf(pm[tid*4], pm[tid*4+1]), fmaxf(pm[tid*4+2], pm[tid*4+3]));
            psum[((long)(bi * CC + tid)) * NBX + blockIdx.x] = s;
            pmax[((long)(bi * CC + tid)) * NBX + blockIdx.x] = m;
        }
    }
}

// ---------------- depthwise 3x3 pad 1, float4, optional row-sumsq partials ----------------
template<bool SQ>
__global__ void __launch_bounds__(256) dw4_kernel(const float* __restrict__ x,
                                                  const float* __restrict__ w,
                                                  float* __restrict__ y,
                                                  float* __restrict__ sqpart) {
    int gidx = blockIdx.x * 256 + threadIdx.x;
    int bc = blockIdx.y;
    int p = gidx * 4;
    int yy = p / WIMG, xx = p % WIMG;
    const float* xp = x + (size_t)bc * PP;
    const float* wc = w + (bc % CC) * 9;
    float w00 = wc[0], w01 = wc[1], w02 = wc[2];
    float w10 = wc[3], w11 = wc[4], w12 = wc[5];
    float w20 = wc[6], w21 = wc[7], w22 = wc[8];

    float4 acc = make_float4(0.f, 0.f, 0.f, 0.f);
    #pragma unroll
    for (int ky = 0; ky < 3; ky++) {
        int sy = yy + ky - 1;
        if ((unsigned)sy >= HIMG) continue;
        const float* row = xp + sy * WIMG + xx;
        float4 c = *(const float4*)row;
        float lf = (xx > 0) ? row[-1] : 0.f;
        float rt = (xx + 4 < WIMG) ? row[4] : 0.f;
        float k0 = (ky == 0) ? w00 : (ky == 1) ? w10 : w20;
        float k1 = (ky == 0) ? w01 : (ky == 1) ? w11 : w21;
        float k2 = (ky == 0) ? w02 : (ky == 1) ? w12 : w22;
        acc.x += k0 * lf  + k1 * c.x + k2 * c.y;
        acc.y += k0 * c.x + k1 * c.y + k2 * c.z;
        acc.z += k0 * c.y + k1 * c.z + k2 * c.w;
        acc.w += k0 * c.z + k1 * c.w + k2 * rt;
    }
    *(float4*)&y[(size_t)bc * PP + p] = acc;

    if (SQ) {
        float s = acc.x*acc.x + acc.y*acc.y + acc.z*acc.z + acc.w*acc.w;
        __shared__ float red[256];
        red[threadIdx.x] = s; __syncthreads();
        for (int o = 128; o > 0; o >>= 1) {
            if (threadIdx.x < o) red[threadIdx.x] += red[threadIdx.x + o];
            __syncthreads();
        }
        if (threadIdx.x == 0) sqpart[bc * NDW + blockIdx.x] = red[0];
    }
}

// ---------------- reduce dw sumsq partials -> norms ----------------
__global__ void normred_kernel(const float* __restrict__ sq, const float* __restrict__ sk,
                               float* __restrict__ nq, float* __restrict__ nk) {
    int r = blockIdx.x * blockDim.x + threadIdx.x;
    if (r >= BB * CC) return;
    float s = 0.f, t = 0.f;
    #pragma unroll 4
    for (int i = 0; i < NDW; i++) { s += sq[r * NDW + i]; t += sk[r * NDW + i]; }
    nq[r] = fmaxf(sqrtf(s), 1e-12f);
    nk[r] = fmaxf(sqrtf(t), 1e-12f);
}

// ---------------- Gram partials ----------------
__global__ void __launch_bounds__(256) gram_partial(const float* __restrict__ q,
                                                    const float* __restrict__ k,
                                                    float* __restrict__ part) {
    int ch = blockIdx.x, bn = blockIdx.y;
    int p0 = ch * CHUNK_PX;
    const float* qb = q + (size_t)bn * HD * PP;
    const float* kb = k + (size_t)bn * HD * PP;
    __shared__ __align__(16) float qs[16][HD];
    __shared__ __align__(16) float ks[16][HD];
    int tid = threadIdx.x;
    int tx = tid % 16, ty = tid / 16;

    float acc[4][4];
    #pragma unroll
    for (int a = 0; a < 4; a++)
        #pragma unroll
        for (int b = 0; b < 4; b++) acc[a][b] = 0.f;

    int li = tid / 4;
    int lt = (tid % 4) * 4;
    for (int t0 = 0; t0 < CHUNK_PX; t0 += 16) {
        float4 qv4 = *(const float4*)&qb[(size_t)li * PP + p0 + t0 + lt];
        float4 kv4 = *(const float4*)&kb[(size_t)li * PP + p0 + t0 + lt];
        qs[lt+0][li] = qv4.x; qs[lt+1][li] = qv4.y; qs[lt+2][li] = qv4.z; qs[lt+3][li] = qv4.w;
        ks[lt+0][li] = kv4.x; ks[lt+1][li] = kv4.y; ks[lt+2][li] = kv4.z; ks[lt+3][li] = kv4.w;
        __syncthreads();
        #pragma unroll
        for (int t = 0; t < 16; t++) {
            float4 qv = *(const float4*)&qs[t][ty*4];
            float4 kv = *(const float4*)&ks[t][tx*4];
            float qa[4] = {qv.x, qv.y, qv.z, qv.w};
            float ka[4] = {kv.x, kv.y, kv.z, kv.w};
            #pragma unroll
            for (int a = 0; a < 4; a++)
                #pragma unroll
                for (int b = 0; b < 4; b++)
                    acc[a][b] = fmaf(qa[a], ka[b], acc[a][b]);
        }
        __syncthreads();
    }
    float* pb = part + (((size_t)bn * NCHUNK + ch) * HD) * HD;
    #pragma unroll
    for (int a = 0; a < 4; a++) {
        int i = ty * 4 + a;
        #pragma unroll
        for (int b = 0; b < 4; b++)
            pb[i * HD + tx * 4 + b] = acc[a][b];
    }
}

// ---------------- reduce + softmax ----------------
__global__ void attn_softmax(const float* __restrict__ part, const float* __restrict__ nq,
                             const float* __restrict__ nk, const float* __restrict__ scale,
                             float* __restrict__ attnw_out, float* __restrict__ a) {
    int bn = blockIdx.x;
    int n = bn % NH;
    int warp = threadIdx.x / 32, lane = threadIdx.x % 32;
    float sc = scale[n];
    for (int i = warp; i < HD; i += 8) {
        float v[2];
        #pragma unroll
        for (int h = 0; h < 2; h++) {
            int j = lane + 32 * h;
            float s = 0.f;
            for (int ch = 0; ch < NCHUNK; ch++)
                s += part[(((size_t)bn * NCHUNK + ch) * HD + i) * HD + j];
            s = s * sc / (nq[bn*HD + i] * nk[bn*HD + j]);
            attnw_out[((size_t)bn * HD + i) * HD + j] = s;
            v[h] = s;
        }
        float m = fmaxf(v[0], v[1]);
        #pragma unroll
        for (int o = 16; o; o >>= 1) m = fmaxf(m, __shfl_xor_sync(0xffffffffu, m, o));
        float e0 = expf(v[0] - m), e1 = expf(v[1] - m);
        float s = e0 + e1;
        #pragma unroll
        for (int o = 16; o; o >>= 1) s += __shfl_xor_sync(0xffffffffu, s, o);
        float inv = 1.0f / s;
        a[((size_t)bn * HD + i) * HD + lane]      = e0 * inv;
        a[((size_t)bn * HD + i) * HD + lane + 32] = e1 * inv;
    }
}

// ---------------- fused a@v + channel-LN ----------------
// out[c,p] = LN_c( sum_d a[head(c)][c&63][d] * v[head(c)*64+d][p] )
// CTA: 128-px tile, all 128 channels. smem: As 32KB + Vs 67.6KB + red 9KB.
#define AV_SMEM (8192*4 + 128*132*4 + (2*1024 + 256)*4)
__global__ void __launch_bounds__(256) avln_kernel(
    const float* __restrict__ a, const float* __restrict__ v,
    const float* __restrict__ lnw, const float* __restrict__ lnb,
    float* __restrict__ t)
{
    extern __shared__ __align__(16) float dsm[];
    float* As = dsm;                    // [2][64][64]
    float* Vs = As + 8192;              // [128][132]
    float* redS = Vs + 128*132;         // [8][128]
    float* redQ = redS + 1024;          // [8][128]
    float* muA  = redQ + 1024;          // [128]
    float* rsA  = muA + 128;            // [128]

    const int tid = threadIdx.x;
    const int bi = blockIdx.y;
    const int p0 = blockIdx.x * 128;

    // load a (both heads of this batch): 8192 floats
    const float* ab = a + (size_t)bi * 2 * 4096;
    #pragma unroll
    for (int it = 0; it < 8; it++) {
        int idx = (it * 256 + tid) * 4;
        *(float4*)&As[idx] = *(const float4*)&ab[idx];
    }
    // load v tile [128ch][128px]
    const float* vb = v + (size_t)bi * CC * PP;
    #pragma unroll
    for (int it = 0; it < 16; it++) {
        int idx = it * 256 + tid;
        int row = idx >> 5, n4 = idx & 31;
        *(float4*)&Vs[row * 132 + n4 * 4] = *(const float4*)&vb[(size_t)row * PP + p0 + n4 * 4];
    }
    __syncthreads();

    const int px4 = tid & 31;          // float4 column
    const int cg = tid >> 5;           // 0..7 -> 16 channels each
    const int h = cg >> 2;
    const int cbase = cg * 16;
    const float* Ah = As + h * 4096;

    float4 acc[16];
    #pragma unroll
    for (int cl = 0; cl < 16; cl++) acc[cl] = make_float4(0.f, 0.f, 0.f, 0.f);

    #pragma unroll
    for (int j4 = 0; j4 < 16; j4++) {
        float4 vv0 = *(float4*)&Vs[(h*64 + j4*4 + 0) * 132 + px4*4];
        float4 vv1 = *(float4*)&Vs[(h*64 + j4*4 + 1) * 132 + px4*4];
        float4 vv2 = *(float4*)&Vs[(h*64 + j4*4 + 2) * 132 + px4*4];
        float4 vv3 = *(float4*)&Vs[(h*64 + j4*4 + 3) * 132 + px4*4];
        #pragma unroll
        for (int cl = 0; cl < 16; cl++) {
            int i = (cbase + cl) & 63;
            float4 a4 = *(float4*)&Ah[i * 64 + j4 * 4];
            acc[cl].x += a4.x*vv0.x + a4.y*vv1.x + a4.z*vv2.x + a4.w*vv3.x;
            acc[cl].y += a4.x*vv0.y + a4.y*vv1.y + a4.z*vv2.y + a4.w*vv3.y;
            acc[cl].z += a4.x*vv0.z + a4.y*vv1.z + a4.z*vv2.z + a4.w*vv3.z;
            acc[cl].w += a4.x*vv0.w + a4.y*vv1.w + a4.z*vv2.w + a4.w*vv3.w;
        }
    }

    // per-pixel LN over the 128 channels (8 cg groups)
    float4 s4 = make_float4(0.f,0.f,0.f,0.f), q4 = make_float4(0.f,0.f,0.f,0.f);
    #pragma unroll
    for (int cl = 0; cl < 16; cl++) {
        s4.x += acc[cl].x; s4.y += acc[cl].y; s4.z += acc[cl].z; s4.w += acc[cl].w;
        q4.x += acc[cl].x*acc[cl].x; q4.y += acc[cl].y*acc[cl].y;
        q4.z += acc[cl].z*acc[cl].z; q4.w += acc[cl].w*acc[cl].w;
    }
    *(float4*)&redS[cg * 128 + px4 * 4] = s4;
    *(float4*)&redQ[cg * 128 + px4 * 4] = q4;
    __syncthreads();
    if (tid < 128) {
        float s = 0.f, q2 = 0.f;
        #pragma unroll
        for (int g = 0; g < 8; g++) { s += redS[g * 128 + tid]; q2 += redQ[g * 128 + tid]; }
        float mu = s * (1.0f / 128.0f);
        float var = q2 * (1.0f / 128.0f) - mu * mu;
        muA[tid] = mu;
        rsA[tid] = rsqrtf(var + 1e-5f);
    }
    __syncthreads();

    float4 mu4 = *(float4*)&muA[px4 * 4];
    float4 rs4 = *(float4*)&rsA[px4 * 4];
    float* tb = t + (size_t)bi * CC * PP;
    #pragma unroll
    for (int cl = 0; cl < 16; cl++) {
        int c = cbase + cl;
        float w = __ldg(&lnw[c]), b = __ldg(&lnb[c]);
        float4 o;
        o.x = (acc[cl].x - mu4.x) * rs4.x * w + b;
        o.y = (acc[cl].y - mu4.y) * rs4.y * w + b;
        o.z = (acc[cl].z - mu4.z) * rs4.z * w + b;
        o.w = (acc[cl].w - mu4.w) * rs4.w * w + b;
        *(float4*)&tb[(size_t)c * PP + p0 + px4 * 4] = o;
    }
}

// ---------------- pool partial reduce + ChannelGate ----------------
__global__ void gate_pool_kernel(const float* __restrict__ psum, const float* __restrict__ pmax,
                                 const float* __restrict__ w1, const float* __restrict__ b1,
                                 const float* __restrict__ w2, const float* __restrict__ b2,
                                 float* __restrict__ out) {
    __shared__ float sa[CC], sm_[CC], ha[8], hm[8];
    int c = threadIdx.x;
    for (int b = 0; b < BB; b++) {
        float s = 0.f, m = -INFINITY;
        long base = (long)(b * CC + c) * NBX;
        for (int i = 0; i < NBX; i++) {
            s += psum[base + i];
            m = fmaxf(m, pmax[base + i]);
        }
        sa[c] = s * (1.0f / PP);
        sm_[c] = m;
        __syncthreads();
        if (c < 8) {
            float xa = b1[c], xm = b1[c];
            for (int cc = 0; cc < CC; cc++) {
                xa += w1[c*CC + cc] * sa[cc];
                xm += w1[c*CC + cc] * sm_[cc];
            }
            ha[c] = fmaxf(xa, 0.f);
            hm[c] = fmaxf(xm, 0.f);
        }
        __syncthreads();
        float xa = b2[c], xm = b2[c];
        #pragma unroll
        for (int j = 0; j < 8; j++) {
            xa += w2[c*8 + j] * ha[j];
            xm += w2[c*8 + j] * hm[j];
        }
        out[b*CC + c] = 1.0f / (1.0f + expf(-(xa + xm)));
        __syncthreads();
    }
}

// ---------------- host launch ----------------
static float* sym(const void* s) {
    void* p = nullptr;
    cudaGetSymbolAddress(&p, s);
    return (float*)p;
}

extern "C" void kernel_launch(void* const* d_in, const int* in_sizes, int n_in,
                              void* d_out, int out_size) {
    const float* x       = (const float*)d_in[0];
    const float* ln_in_w = (const float*)d_in[1];
    const float* ln_in_b = (const float*)d_in[2];
    const float* wq_pw   = (const float*)d_in[3];
    const float* wq_dw   = (const float*)d_in[4];
    const float* wk_pw   = (const float*)d_in[5];
    const float* wk_dw   = (const float*)d_in[6];
    const float* wv_pw   = (const float*)d_in[7];
    const float* wv_dw   = (const float*)d_in[8];
    const float* scale   = (const float*)d_in[9];
    const float* ln_o_w  = (const float*)d_in[10];
    const float* ln_o_b  = (const float*)d_in[11];
    const float* f1_pw   = (const float*)d_in[12];
    const float* f1_dw   = (const float*)d_in[13];
    const float* f2_pw   = (const float*)d_in[14];
    const float* f2_dw   = (const float*)d_in[15];
    const float* f_out   = (const float*)d_in[16];
    const float* g_w1    = (const float*)d_in[17];
    const float* g_b1    = (const float*)d_in[18];
    const float* g_w2    = (const float*)d_in[19];
    const float* g_b2    = (const float*)d_in[20];
    float* out = (float*)d_out;

    float* t  = sym(g_t);   float* t2 = sym(g_t2);  float* t3 = sym(g_t3);
    float* q  = sym(g_q);   float* k  = sym(g_k);   float* v  = sym(g_v);
    float* nq = sym(g_norm_q); float* nk = sym(g_norm_k);
    float* part = sym(g_part); float* a = sym(g_a);
    float* sqq = sym(g_sqq);   float* sqk = sym(g_sqk);
    float* psum = sym(g_psum); float* pmax = sym(g_pmax);

    auto qkv  = gemm_fused<1,3,true, false,false,false,true>;
    auto f1f2 = gemm_fused<1,2,false,false,true, false,true>;
    auto fout = gemm_fused<2,1,false,true, false,true, false>;
    cudaFuncSetAttribute(qkv,  cudaFuncAttributeMaxDynamicSharedMemorySize, MM_SMEM_LN);
    cudaFuncSetAttribute(f1f2, cudaFuncAttributeMaxDynamicSharedMemorySize, MM_SMEM);
    cudaFuncSetAttribute(fout, cudaFuncAttributeMaxDynamicSharedMemorySize, MM_SMEM);
    cudaFuncSetAttribute(avln_kernel, cudaFuncAttributeMaxDynamicSharedMemorySize, AV_SMEM);

    const long SB = (long)CC * PP;
    dim3 gGrid(NBX, BB);
    dim3 dwGrid(NDW, BB*CC);
    dim3 avGrid(NBX, BB);

    // 1) fused LN + QKV pointwise
    qkv<<<gGrid, 256, MM_SMEM_LN>>>(wq_pw, wk_pw, wv_pw, x, nullptr, SB,
                                    ln_in_w, ln_in_b, t, t2, t3, SB, nullptr, nullptr);
    // 2) depthwise (+ sumsq partials for q,k)
    dw4_kernel<true ><<<dwGrid, 256>>>(t,  wq_dw, q, sqq);
    dw4_kernel<true ><<<dwGrid, 256>>>(t2, wk_dw, k, sqk);
    dw4_kernel<false><<<dwGrid, 256>>>(t3, wv_dw, v, nullptr);
    // 3) norms
    normred_kernel<<<2, 256>>>(sqq, sqk, nq, nk);
    // 4) Gram + softmax (attn_weight -> d_out + 512)
    gram_partial<<<dim3(NCHUNK, BNH), 256>>>(q, k, part);
    attn_softmax<<<BNH, 256>>>(part, nq, nk, scale, out + BB*CC, a);
    // 5) fused a@v + LN -> t
    avln_kernel<<<avGrid, 256, AV_SMEM>>>(a, v, ln_o_w, ln_o_b, t);
    // 6) fused f1+f2 pointwise (GELU out) -> t2, t3
    f1f2<<<gGrid, 256, MM_SMEM>>>(f1_pw, f2_pw, nullptr, t, nullptr, SB,
                                  nullptr, nullptr, t2, t3, nullptr, SB, nullptr, nullptr);
    // 7) depthwise FFN branches
    dw4_kernel<false><<<dwGrid, 256>>>(t2, f1_dw, q, nullptr);
    dw4_kernel<false><<<dwGrid, 256>>>(t3, f2_dw, k, nullptr);
    // 8) f_out (GELU in, K=256) -> pool partials only
    fout<<<gGrid, 256, MM_SMEM>>>(f_out, nullptr, nullptr, q, k, SB,
                                  nullptr, nullptr, nullptr, nullptr, nullptr, SB, psum, pmax);
    // 9) ChannelGate
    gate_pool_kernel<<<1, 128>>>(psum, pmax, g_w1, g_b1, g_w2, g_b2, out);
}